// round 15
// baseline (speedup 1.0000x reference)
#include <cuda_runtime.h>
#include <math.h>
#include <stdint.h>

#define T     128
#define H     1024
#define INTER 4096
#define NE    8
#define NSTG  5

// ---------------- device-global scratch ----------------
__device__ int   g_cnt[NE];
__device__ int   g_tok[NE][T];
__device__ float g_coef[NE][T];           // pad slots never written -> stay 0
// chunk-packed tf32-rounded fp32 activations: [e][k-chunk][m][32 k]
__device__ float g_xg[NE][32][T][32];     // gathered token rows (4.2 MB)
__device__ float g_act[NE][128][T][32];   // coef-scaled swiglu output (16.8 MB)

// ---------------- smem layout (dynamic) ----------------
// [0,512)   coefs (fc1) / toks (fc2)
// [512,512+NSTG*16)  mbarriers: per stage [full(8B), empty(8B)]
// [1024, +NSTG*20480)  stages: A 4KB + B 16KB, fp32 128B rows,
//                      16B unit u of row r stored at u ^ (r & 7).
#define ST_OFF   1024
#define STG_B    4096
#define STAGEB   20480
#define SMEM_BYTES (1024 + NSTG * STAGEB)   // 103424

// ---------------- PTX helpers ----------------
static __device__ __forceinline__ uint32_t smem_u32(const void* p){
    uint32_t a;
    asm("{ .reg .u64 t; cvta.to.shared.u64 t, %1; cvt.u32.u64 %0, t; }" : "=r"(a) : "l"(p));
    return a;
}
#define CP16(d, s)  asm volatile("cp.async.cg.shared.global [%0], [%1], 16;" :: "r"(d), "l"(s) : "memory")
#define MBAR_INIT(a, n) asm volatile("mbarrier.init.shared.b64 [%0], %1;" :: "r"(a), "r"(n) : "memory")
#define MBAR_ARRIVE(a)  asm volatile("mbarrier.arrive.shared.b64 _, [%0];" :: "r"(a) : "memory")
#define CP_ARRIVE(a)    asm volatile("cp.async.mbarrier.arrive.noinc.shared.b64 [%0];" :: "r"(a) : "memory")

static __device__ __forceinline__ void mbar_wait(uint32_t a, uint32_t ph){
    asm volatile("{\n\t.reg .pred P1;\n\tLW_%=:\n\t"
        "mbarrier.try_wait.parity.acquire.cta.shared::cta.b64 P1, [%0], %1, 0x989680;\n\t"
        "@P1 bra LD_%=;\n\tbra LW_%=;\n\tLD_%=:\n\t}"
        :: "r"(a), "r"(ph) : "memory");
}

static __device__ __forceinline__ uint32_t f2tf(float x){
    uint32_t r; asm("cvt.rna.tf32.f32 %0, %1;" : "=r"(r) : "f"(x)); return r;
}
static __device__ __forceinline__ uint32_t rnd_bits(uint32_t b){
    return f2tf(__uint_as_float(b));
}
#define LDM4(r, addr) \
    asm volatile("ldmatrix.sync.aligned.m8n8.x4.shared.b16 {%0,%1,%2,%3}, [%4];" \
        : "=r"((r)[0]), "=r"((r)[1]), "=r"((r)[2]), "=r"((r)[3]) : "r"(addr))

static __device__ __forceinline__ void mma8(float* d, const uint32_t* a, uint32_t b0, uint32_t b1){
    asm volatile("mma.sync.aligned.m16n8k8.row.col.f32.tf32.tf32.f32 "
        "{%0,%1,%2,%3}, {%4,%5,%6,%7}, {%8,%9}, {%0,%1,%2,%3};"
        : "+f"(d[0]), "+f"(d[1]), "+f"(d[2]), "+f"(d[3])
        : "r"(a[0]), "r"(a[1]), "r"(a[2]), "r"(a[3]), "r"(b0), "r"(b1));
}

// ---------------- kernel 1: routing ----------------
__global__ void route_kernel(const float* __restrict__ routing) {
    __shared__ int s_cnt[NE];
    int t = threadIdx.x;
    if (t < NE) s_cnt[t] = 0;
    __syncthreads();
    float r[NE];
#pragma unroll
    for (int e = 0; e < NE; e++) r[e] = routing[t * NE + e];
    int i0 = 0;
#pragma unroll
    for (int e = 1; e < NE; e++) if (r[e] > r[i0]) i0 = e;
    int i1 = (i0 == 0) ? 1 : 0;
#pragma unroll
    for (int e = 0; e < NE; e++) if (e != i0 && r[e] > r[i1]) i1 = e;
    float d  = expf(r[i1] - r[i0]);
    float s0 = 1.0f / (1.0f + d);
    float s1 = d / (1.0f + d);
    int p0 = atomicAdd(&s_cnt[i0], 1);
    int p1 = atomicAdd(&s_cnt[i1], 1);
    g_tok[i0][p0] = t;  g_coef[i0][p0] = s0;
    g_tok[i1][p1] = t;  g_coef[i1][p1] = s1;
    __syncthreads();
    if (t < NE) g_cnt[t] = s_cnt[t];
}

// ---------------- kernel 2: gather token rows (tf32-rounded, chunk-packed) + zero out ----
__global__ void gather_x_kernel(const float* __restrict__ x, float* __restrict__ out) {
    int bid = blockIdx.x;
    int e = bid >> 7, m = bid & 127;
    int t = threadIdx.x;
    out[bid * 128 + t] = 0.0f;
    int tok = (m < g_cnt[e]) ? g_tok[e][m] : 0;
    const float4* src = (const float4*)(x + (size_t)tok * H);
    float4 v0 = src[2 * t];
    float4 v1 = src[2 * t + 1];
    uint4 o0, o1;
    o0.x = f2tf(v0.x); o0.y = f2tf(v0.y); o0.z = f2tf(v0.z); o0.w = f2tf(v0.w);
    o1.x = f2tf(v1.x); o1.y = f2tf(v1.y); o1.z = f2tf(v1.z); o1.w = f2tf(v1.w);
    uint4* dst = (uint4*)&g_xg[e][t >> 2][m][(t & 3) * 8];
    dst[0] = o0; dst[1] = o1;
}

// ================= GEMM machinery =================
// Consumer: CTA tile M=32 x N=128 x Kchunk=32 (4 tf32 k8 steps); 8 consumer
// warps, warp tile 32x16. Arithmetic bit-identical to R13/R14.
static __device__ __forceinline__ void compute_chunk(
        uint32_t aAf0, uint32_t aAf1, uint32_t aBf, float (&acc)[2][2][4]) {
#pragma unroll
    for (int ks = 0; ks < 4; ks++) {
        uint32_t x = ks << 5;
        uint32_t a0[4], a1[4], b[4];
        LDM4(a0, aAf0 ^ x);
        LDM4(a1, aAf1 ^ x);
        LDM4(b,  aBf  ^ x);
        b[0] = rnd_bits(b[0]); b[1] = rnd_bits(b[1]);
        b[2] = rnd_bits(b[2]); b[3] = rnd_bits(b[3]);
        mma8(acc[0][0], a0, b[0], b[2]);
        mma8(acc[0][1], a0, b[1], b[3]);
        mma8(acc[1][0], a1, b[0], b[2]);
        mma8(acc[1][1], a1, b[1], b[3]);
    }
}

// Producer loop: 64 threads (warps 8-9) own all cp.async; mbarrier handshake.
// A: thread p -> row p>>1, units (p&1)*4 .. +3 (contiguous 64B per thread).
// B: thread p -> rows (p>>3)+8j (j=0..15), unit p&7; each warp-instruction
//    covers 4 complete consecutive rows -> fully coalesced 512B.
#define PRODUCER_LOOP(NK) do { \
    int p  = tid - 256; \
    int ar = p >> 1, ub = (p & 1) * 4; \
    uint32_t dA[4]; \
    _Pragma("unroll") for (int _j = 0; _j < 4; _j++) \
        dA[_j] = smemA + (uint32_t)ar * 128 + ((((uint32_t)(ub + _j)) ^ (ar & 7)) << 4); \
    int rp = p >> 3, up = p & 7; \
    uint32_t dB = smemB + (uint32_t)rp * 128 + (((uint32_t)up ^ rp) << 4); \
    int stg = 0, ph = 1; \
    for (int i = 0; i < (NK); i++) { \
        mbar_wait(mb + stg * 16 + 8, ph);                 /* empty[stg] */ \
        uint32_t so = (uint32_t)stg * STAGEB; \
        const float* as = aglob + (size_t)i * 4096; \
        CP16(dA[0] + so, as);     CP16(dA[1] + so, as + 4); \
        CP16(dA[2] + so, as + 8); CP16(dA[3] + so, as + 12); \
        _Pragma("unroll") for (int _j = 0; _j < 8; _j++) \
            CP16(dB + (uint32_t)_j * 1024 + so, bsrc0 + (size_t)8 * _j * BRS + (size_t)i * 32); \
        _Pragma("unroll") for (int _j = 0; _j < 8; _j++) \
            CP16(dB + (uint32_t)(_j + 8) * 1024 + so, bsrc1 + (size_t)8 * _j * BRS + (size_t)i * 32); \
        CP_ARRIVE(mb + stg * 16);                         /* full[stg] on cp completion */ \
        if (++stg == NSTG) { stg = 0; ph ^= 1; } \
    } \
} while (0)

#define CONSUMER_SETUP() \
    uint32_t smemA_ = smemA, smemB_ = smemB; (void)smemA_; (void)smemB_; \
    int ls = lane & 7, h3 = (lane >> 3) & 1, h4 = (lane >> 4) & 1; \
    uint32_t amr = (uint32_t)(8 * h3 + ls); \
    uint32_t aAf0 = smemA + amr * 128 + (((uint32_t)h4 ^ ls) << 4); \
    uint32_t aAf1 = aAf0 + 16 * 128; \
    uint32_t bnr = (uint32_t)(wid * 16 + 8 * h3 + ls); \
    uint32_t aBf = smemB + bnr * 128 + (((uint32_t)h4 ^ ls) << 4); \
    float acc[2][2][4]; \
    _Pragma("unroll") for (int _m = 0; _m < 2; _m++) \
    _Pragma("unroll") for (int _j = 0; _j < 2; _j++) \
    _Pragma("unroll") for (int _q = 0; _q < 4; _q++) acc[_m][_j][_q] = 0.0f;

#define CONSUMER_LOOP(NK) do { \
    int stg = 0, ph = 0; \
    for (int i = 0; i < (NK); i++) { \
        mbar_wait(mb + stg * 16, ph);                     /* full[stg] */ \
        uint32_t so = (uint32_t)stg * STAGEB; \
        compute_chunk(aAf0 + so, aAf1 + so, aBf + so, acc); \
        MBAR_ARRIVE(mb + stg * 16 + 8);                   /* empty[stg] */ \
        if (++stg == NSTG) { stg = 0; ph ^= 1; } \
    } \
} while (0)

#define BAR_CONSUMERS() asm volatile("bar.sync 1, 256;" ::: "memory")

// ---------------- kernel 3: fc1 GEMM + fused swiglu + coef fold ----------------
// grid (4, 64, NE), 320 threads (8 consumer + 2 producer warps).
// B tile rows 0-63 = up channels n0.., 64-127 = gate channels INTER+n0..
__global__ void __launch_bounds__(320, 2) fc1_mma(const float* __restrict__ w1) {
    extern __shared__ __align__(1024) char smem[];
    float* coefs = (float*)smem;

    int e   = blockIdx.z;
    int cnt = g_cnt[e];
    int m0g = blockIdx.x * 32;
    if (m0g >= cnt) return;
    int n0  = blockIdx.y * 64;

    int tid = threadIdx.x, wid = tid >> 5, lane = tid & 31;
    uint32_t sbase = smem_u32(smem);
    uint32_t smemA = sbase + ST_OFF;
    uint32_t smemB = smemA + STG_B;
    uint32_t mb    = sbase + 512;

    if (tid == 0) {
#pragma unroll
        for (int s = 0; s < NSTG; s++) {
            MBAR_INIT(mb + s * 16, 64);        // full: 64 producer threads
            MBAR_INIT(mb + s * 16 + 8, 256);   // empty: 256 consumer threads
        }
    }
    if (tid < 32) coefs[tid] = g_coef[e][m0g + tid];   // pads = 0
    __syncthreads();

    if (tid >= 256) {
        // ---------------- producer warps ----------------
        int p  = tid - 256;
        int ar = p >> 1;
        int ub = (p & 1) * 4;
        int rp = p >> 3, up = p & 7;
        const float* aglob = &g_xg[e][0][m0g][0] + ar * 32 + ub * 4;
        const float* w1e   = w1 + (size_t)e * (2 * INTER) * H;
        const float* bsrc0 = w1e + (size_t)(n0 + rp) * H + up * 4;           // up rows
        const float* bsrc1 = w1e + (size_t)(INTER + n0 + rp) * H + up * 4;   // gate rows
        const intptr_t BRS = H;
        PRODUCER_LOOP(32);
        return;
    }

    // ---------------- consumer warps ----------------
    CONSUMER_SETUP();
    CONSUMER_LOOP(32);

    // ---- epilogue: exchange via smem, swiglu + coef, tf32-rounded store to g_act ----
    BAR_CONSUMERS();
    float* buf = (float*)(smem + ST_OFF);   // 32 x 132 fp32 (stage area, producers done)
    int g0 = lane >> 2, t4 = lane & 3;
#pragma unroll
    for (int mf = 0; mf < 2; mf++) {
        int r0 = mf * 16 + g0;
#pragma unroll
        for (int nf = 0; nf < 2; nf++) {
            int j = wid * 16 + nf * 8 + 2 * t4;
            buf[r0 * 132 + j]           = acc[mf][nf][0];
            buf[r0 * 132 + j + 1]       = acc[mf][nf][1];
            buf[(r0 + 8) * 132 + j]     = acc[mf][nf][2];
            buf[(r0 + 8) * 132 + j + 1] = acc[mf][nf][3];
        }
    }
    BAR_CONSUMERS();
    {
        int m  = tid >> 3;
        int cb = (tid & 7) * 8;
        float c = coefs[m];
        const float* row = &buf[m * 132];
        uint32_t w[8];
#pragma unroll
        for (int q = 0; q < 8; q++) {
            float u = row[cb + q];
            float g = row[64 + cb + q];
            w[q] = f2tf(c * (u / (1.0f + __expf(-u))) * g);
        }
        uint4* dst = (uint4*)&g_act[e][(n0 + cb) >> 5][m0g + m][cb & 31];
        uint4 p0, p1;
        p0.x = w[0]; p0.y = w[1]; p0.z = w[2]; p0.w = w[3];
        p1.x = w[4]; p1.y = w[5]; p1.z = w[6]; p1.w = w[7];
        dst[0] = p0; dst[1] = p1;
    }
}

// ---------------- kernel 4: fc2 GEMM (8-way K-split) + scatter-add ----------------
// grid (4, 64, NE): x = m-tile (fastest), y = n-tile(8) x k-slice(8). K-slice = 512.
__global__ void __launch_bounds__(320, 2) fc2_mma(const float* __restrict__ w2,
                                                  float* __restrict__ out) {
    extern __shared__ __align__(1024) char smem[];
    int* toks = (int*)smem;

    int e   = blockIdx.z;
    int cnt = g_cnt[e];
    int m0g = blockIdx.x * 32;
    if (m0g >= cnt) return;
    int n0    = (blockIdx.y >> 3) * 128;
    int kbase = (blockIdx.y & 7) * 512;

    int tid = threadIdx.x, wid = tid >> 5, lane = tid & 31;
    uint32_t sbase = smem_u32(smem);
    uint32_t smemA = sbase + ST_OFF;
    uint32_t smemB = smemA + STG_B;
    uint32_t mb    = sbase + 512;

    if (tid == 0) {
#pragma unroll
        for (int s = 0; s < NSTG; s++) {
            MBAR_INIT(mb + s * 16, 64);
            MBAR_INIT(mb + s * 16 + 8, 256);
        }
    }
    if (tid < 32) toks[tid] = (m0g + tid < cnt) ? g_tok[e][m0g + tid] : 0;
    __syncthreads();

    if (tid >= 256) {
        // ---------------- producer warps ----------------
        int p  = tid - 256;
        int ar = p >> 1;
        int ub = (p & 1) * 4;
        int rp = p >> 3, up = p & 7;
        const float* aglob = &g_act[e][kbase >> 5][m0g][0] + ar * 32 + ub * 4;
        const float* w2e   = w2 + (size_t)e * H * INTER;
        const float* bsrc0 = w2e + (size_t)(n0 + rp) * INTER + kbase + up * 4;
        const float* bsrc1 = bsrc0 + (size_t)64 * INTER;
        const intptr_t BRS = INTER;
        PRODUCER_LOOP(16);
        return;
    }

    // ---------------- consumer warps ----------------
    CONSUMER_SETUP();
    CONSUMER_LOOP(16);

    int g0 = lane >> 2, t4 = lane & 3;
#pragma unroll
    for (int mf = 0; mf < 2; mf++) {
        int r0 = mf * 16 + g0;
#pragma unroll
        for (int nf = 0; nf < 2; nf++) {
            int n = n0 + wid * 16 + nf * 8 + 2 * t4;
            if (m0g + r0 < cnt) {
                float* o = out + (size_t)toks[r0] * H + n;
                atomicAdd(o,     acc[mf][nf][0]);
                atomicAdd(o + 1, acc[mf][nf][1]);
            }
            if (m0g + r0 + 8 < cnt) {
                float* o = out + (size_t)toks[r0 + 8] * H + n;
                atomicAdd(o,     acc[mf][nf][2]);
                atomicAdd(o + 1, acc[mf][nf][3]);
            }
        }
    }
}

// ---------------- launch ----------------
extern "C" void kernel_launch(void* const* d_in, const int* in_sizes, int n_in,
                              void* d_out, int out_size) {
    const float* x       = (const float*)d_in[0];   // [128, 1024]
    const float* routing = (const float*)d_in[1];   // [128, 8]
    const float* w1      = (const float*)d_in[2];   // [8, 8192, 1024]
    const float* w2      = (const float*)d_in[3];   // [8, 1024, 4096]
    float* out = (float*)d_out;                     // [128, 1024]

    cudaFuncSetAttribute(fc1_mma, cudaFuncAttributeMaxDynamicSharedMemorySize, SMEM_BYTES);
    cudaFuncSetAttribute(fc2_mma, cudaFuncAttributeMaxDynamicSharedMemorySize, SMEM_BYTES);

    route_kernel<<<1, T>>>(routing);
    gather_x_kernel<<<NE * T, 128>>>(x, out);
    fc1_mma<<<dim3(4, 64, NE), 320, SMEM_BYTES>>>(w1);
    fc2_mma<<<dim3(4, 64, NE), 320, SMEM_BYTES>>>(w2, out);
}